// round 9
// baseline (speedup 1.0000x reference)
#include <cuda_runtime.h>
#include <cstdint>
#include <math.h>

#define BB 2048
#define NN 200
#define HH 128
#define TT 180

__device__ __forceinline__ float neg_inf() { return __int_as_float(0xff800000); }

// v = W^T (W x[cur] + bias), result in vsm. Uses qsm/vpart/xrow scratch.
__device__ __forceinline__ void compute_v(
    const float* __restrict__ xb, int cur,
    const float* __restrict__ W, const float* __restrict__ bias,
    float* vsm, float* vpart, float* qsm, float* xrow,
    int tid, int lane, int wid)
{
    if (tid < 32)
        *(float4*)(xrow + tid * 4) = *(const float4*)(xb + (size_t)cur * HH + tid * 4);
    __syncthreads();
    {   // q[o] = W[o,:]·x + b[o], warp-per-row, coalesced f4
        float4 xc = *(const float4*)(xrow + lane * 4);
        #pragma unroll
        for (int r = 0; r < 16; r++) {
            int o = wid + r * 8;
            float4 w4 = *(const float4*)(W + (size_t)o * HH + lane * 4);
            float p = fmaf(w4.x, xc.x, fmaf(w4.y, xc.y,
                      fmaf(w4.z, xc.z, w4.w * xc.w)));
            #pragma unroll
            for (int off = 16; off > 0; off >>= 1)
                p += __shfl_xor_sync(0xffffffffu, p, off);
            if (lane == 0) qsm[o] = p + bias[o];
        }
    }
    __syncthreads();
    {   // v[h] = sum_o W[o][h] q[o], coalesced column sweep, o halved
        int h = tid & 127, half = tid >> 7;
        float acc = 0.f;
        const float* Wp = W + (size_t)(half * 64) * HH + h;
        const float* qp = qsm + half * 64;
        #pragma unroll 8
        for (int o = 0; o < 64; o++)
            acc = fmaf(Wp[(size_t)o * HH], qp[o], acc);
        if (half == 0) vsm[h] = acc; else vpart[h] = acc;
    }
    __syncthreads();
    if (tid < HH) vsm[tid] += vpart[tid];
    __syncthreads();
}

__global__ void __launch_bounds__(256, 6)
k_route(const float* __restrict__ x, const float* __restrict__ W,
        const float* __restrict__ bias, const float* __restrict__ coords,
        const float* __restrict__ demands, const float* __restrict__ capacity,
        const int* __restrict__ nsteps, float* __restrict__ out, int out_size) {
    __shared__ float cx[NN], cy[NN], dem[NN];
    __shared__ float vsm[HH], vpart[HH], qsm[HH], xrow[HH];
    __shared__ int vis[NN];
    __shared__ float red[32];
    __shared__ int redi[32], nxt_s;

    const int tid  = threadIdx.x;
    const int b    = blockIdx.x;
    const int lane = tid & 31;
    const int wid  = tid >> 5;
    const int g    = lane >> 3;      // group 0..3
    const int j    = lane & 7;       // lane-in-group
    const int nbase = wid + 8 * g;   // 0..31

    const int T = nsteps ? nsteps[0] : TT;
    const float* xb = x + (size_t)b * NN * HH;

    // ---- ownership-based zeroing: own action row + share of tail ------------
    if (tid < T) out[(size_t)b * T + tid] = 0.0f;
    {
        long long tail = (long long)out_size - (long long)BB * T;
        if (tail > 0) {
            int chunk = (int)((tail + BB - 1) / BB);
            long long s0 = (long long)BB * T + (long long)b * chunk;
            for (int i = tid; i < chunk; i += 256) {
                long long idx = s0 + i;
                if (idx < out_size) out[idx] = 0.0f;
            }
        }
    }

    // ---- stage per-batch aux -------------------------------------------------
    {
        const float2* cb2 = (const float2*)(coords + (size_t)b * NN * 2);
        const float*  db  = demands + (size_t)b * NN;
        if (tid < NN) {
            float2 c2 = cb2[tid];
            cx[tid] = c2.x; cy[tid] = c2.y;
            dem[tid] = db[tid];
            vis[tid] = 0;
        }
    }
    __syncthreads();

    // ---- v for cur=0 (inline; W is L2-hot after first wave) ------------------
    compute_v(xb, 0, W, bias, vsm, vpart, qsm, xrow, tid, lane, wid);

    const float cap = capacity[b];
    float rem = cap;
    int cur = 0;

    for (int step = 0; step < T; step++) {
        // stage v into regs: lane j covers h = 32*i + 4j, i=0..3
        float4 vr0 = *(const float4*)(vsm +   0 + j * 4);
        float4 vr1 = *(const float4*)(vsm +  32 + j * 4);
        float4 vr2 = *(const float4*)(vsm +  64 + j * 4);
        float4 vr3 = *(const float4*)(vsm +  96 + j * 4);
        float cxc = cx[cur], cyc = cy[cur];

        float best = neg_inf();
        int bidx = NN;
        // group handles nodes n = nbase + 32k (ascending -> strict > keeps lowest)
        #pragma unroll 2
        for (int k = 0; k < 7; k++) {
            int n = nbase + 32 * k;
            bool valid = (n < NN);
            float p = 0.f;
            if (valid) {
                const float* xr = xb + (size_t)n * HH + j * 4;
                float4 a0 = *(const float4*)(xr);
                float4 a1 = *(const float4*)(xr + 32);
                float4 a2 = *(const float4*)(xr + 64);
                float4 a3 = *(const float4*)(xr + 96);
                p = fmaf(a0.x, vr0.x, fmaf(a0.y, vr0.y, fmaf(a0.z, vr0.z, a0.w * vr0.w)));
                p = fmaf(a1.x, vr1.x, fmaf(a1.y, vr1.y, fmaf(a1.z, vr1.z, fmaf(a1.w, vr1.w, p))));
                p = fmaf(a2.x, vr2.x, fmaf(a2.y, vr2.y, fmaf(a2.z, vr2.z, fmaf(a2.w, vr2.w, p))));
                p = fmaf(a3.x, vr3.x, fmaf(a3.y, vr3.y, fmaf(a3.z, vr3.z, fmaf(a3.w, vr3.w, p))));
            }
            // 3-level butterfly within the 8-lane group (4 nodes reduced at once)
            p += __shfl_xor_sync(0xffffffffu, p, 4);
            p += __shfl_xor_sync(0xffffffffu, p, 2);
            p += __shfl_xor_sync(0xffffffffu, p, 1);
            float s = neg_inf();
            if (valid) {
                float dx = cx[n] - cxc, dy = cy[n] - cyc;
                s = p - 0.1f * sqrtf(dx * dx + dy * dy);
                if (n != 0 && (vis[n] || (dem[n] > rem))) s = neg_inf();
            }
            if (s > best) { best = s; bidx = n; }
        }
        if (j == 0) { red[wid * 4 + g] = best; redi[wid * 4 + g] = bidx; }
        __syncthreads();
        // warp 0: tie-broken argmax over 32 candidates (first-index rule)
        if (wid == 0) {
            float bv = red[lane]; int bi = redi[lane];
            #pragma unroll
            for (int off = 16; off > 0; off >>= 1) {
                float ov = __shfl_xor_sync(0xffffffffu, bv, off);
                int   oi = __shfl_xor_sync(0xffffffffu, bi, off);
                if (ov > bv || (ov == bv && oi < bi)) { bv = ov; bi = oi; }
            }
            if (lane == 0) {
                nxt_s = bi;
                vis[bi] = 1;
                out[(size_t)b * T + step] = (float)bi;
            }
        }
        __syncthreads();
        int nxt = nxt_s;
        rem = (nxt == 0) ? cap : (rem - dem[nxt]);
        int prev = cur;
        cur = nxt;
        // depot fixed point: identical state recurs -> all remaining actions 0
        // (row already zeroed by this CTA). Exact, not approximate.
        if (prev == 0 && nxt == 0) break;

        // live path (rare): recompute v for new cur
        compute_v(xb, cur, W, bias, vsm, vpart, qsm, xrow, tid, lane, wid);
    }
}

extern "C" void kernel_launch(void* const* d_in, const int* in_sizes, int n_in,
                              void* d_out, int out_size) {
    const float* x        = (const float*)d_in[0];
    const float* W        = (const float*)d_in[1];
    const float* bias     = (const float*)d_in[2];
    const float* coords   = (const float*)d_in[3];
    const float* demands  = (const float*)d_in[4];
    const float* capacity = (const float*)d_in[5];
    const int*   nsteps   = (n_in > 6) ? (const int*)d_in[6] : nullptr;
    float* out = (float*)d_out;

    k_route<<<BB, 256>>>(x, W, bias, coords, demands, capacity, nsteps, out, out_size);
}

// round 13
// speedup vs baseline: 1.2145x; 1.2145x over previous
#include <cuda_runtime.h>
#include <cstdint>
#include <math.h>

#define BB 2048
#define NN 200
#define HH 128
#define TT 180
#define NGRP 128          // producer groups, 16 batches each

__device__ float g_V0[BB * HH];   // V0[b] = W^T (W x[b,0] + bias)
__device__ int   g_flag[NGRP];    // zero-init; set stays benign across replays

__device__ __forceinline__ float neg_inf() { return __int_as_float(0xff800000); }

__global__ void __launch_bounds__(256, 6)
k_route(const float* __restrict__ x, const float* __restrict__ W,
        const float* __restrict__ bias, const float* __restrict__ coords,
        const float* __restrict__ demands, const float* __restrict__ capacity,
        const int* __restrict__ nsteps, float* __restrict__ out, int out_size) {
    __shared__ float buf[4096];                  // 16KB union
    // ---- route-phase aliases ----
    float* cx   = buf;            float* cy    = buf + 200;
    float* dem  = buf + 400;      int*   vis   = (int*)(buf + 600);
    float* vsm  = buf + 800;      float* vpart = buf + 928;
    float* qsm  = buf + 1056;     float* xrow  = buf + 1184;
    float* red  = buf + 1312;     int*   redi  = (int*)(buf + 1320);
    int*   nxtp = (int*)(buf + 1328);
    // ---- producer-phase aliases (used before route arrays are written) ----
    float* xs = buf;              // [16][128]
    float* qs = buf + 2048;       // [16][128]

    const int tid  = threadIdx.x;
    const int b    = blockIdx.x;
    const int lane = tid & 31;
    const int wid  = tid >> 5;
    const int T    = nsteps ? nsteps[0] : TT;

    // ================= producers: CTA g computes V0 for batches 16g..16g+15 ==
    if (b < NGRP) {
        const int gb0 = b * 16;
        for (int idx = tid; idx < 16 * 32; idx += 256) {
            int r = idx >> 5, jj = idx & 31;
            *(float4*)(xs + r * HH + jj * 4) =
                *(const float4*)(x + (size_t)(gb0 + r) * NN * HH + jj * 4);
        }
        __syncthreads();
        {   // phase 1: q[j][o] = W[o,:]·x0[j] + bias[o]  (W row L1-cached)
            const int o = tid & 127, jb = (tid >> 7) * 8;
            float acc[8];
            float bo = bias[o];
            #pragma unroll
            for (int jj = 0; jj < 8; jj++) acc[jj] = bo;
            for (int h = 0; h < HH; h += 4) {
                float4 w4 = *(const float4*)(W + (size_t)o * HH + h);
                #pragma unroll
                for (int jj = 0; jj < 8; jj++) {
                    float4 xv = *(const float4*)(xs + (jb + jj) * HH + h);
                    acc[jj] = fmaf(w4.x, xv.x, fmaf(w4.y, xv.y,
                              fmaf(w4.z, xv.z, fmaf(w4.w, xv.w, acc[jj]))));
                }
            }
            #pragma unroll
            for (int jj = 0; jj < 8; jj++) qs[(jb + jj) * HH + o] = acc[jj];
        }
        __syncthreads();
        {   // phase 2: V0[j][h] = sum_o W[o][h] q[j][o]  (coalesced W columns)
            const int h = tid & 127, jb = (tid >> 7) * 8;
            float acc[8];
            #pragma unroll
            for (int jj = 0; jj < 8; jj++) acc[jj] = 0.f;
            #pragma unroll 4
            for (int o = 0; o < HH; o++) {
                float w = W[(size_t)o * HH + h];
                #pragma unroll
                for (int jj = 0; jj < 8; jj++)
                    acc[jj] = fmaf(w, qs[(jb + jj) * HH + o], acc[jj]);
            }
            #pragma unroll
            for (int jj = 0; jj < 8; jj++)
                g_V0[(size_t)(gb0 + jb + jj) * HH + h] = acc[jj];
        }
        __threadfence();
        __syncthreads();
        if (tid == 0) atomicExch(&g_flag[b], 1);
    }

    // ================= prologue (overlaps with producers) =====================
    if (tid < T) out[(size_t)b * T + tid] = 0.0f;        // own action row
    {
        long long tail = (long long)out_size - (long long)BB * T;
        if (tail > 0) {                                   // share of log_probs tail
            int chunk = (int)((tail + BB - 1) / BB);
            long long s0 = (long long)BB * T + (long long)b * chunk;
            for (int i = tid; i < chunk; i += 256) {
                long long idx = s0 + i;
                if (idx < out_size) out[idx] = 0.0f;
            }
        }
    }
    __syncthreads();                                      // producer scratch dead
    {
        const float2* cb2 = (const float2*)(coords + (size_t)b * NN * 2);
        const float*  db  = demands + (size_t)b * NN;
        if (tid < NN) {
            float2 c2 = cb2[tid];
            cx[tid] = c2.x; cy[tid] = c2.y;
            dem[tid] = db[tid];
            vis[tid] = 0;
        }
    }
    // wait for this batch's V0 (producers are all wave-1 resident: no deadlock)
    if (tid == 0) {
        while (atomicAdd(&g_flag[b >> 4], 0) == 0) __nanosleep(64);
        __threadfence();
    }
    __syncthreads();
    if (tid < HH) vsm[tid] = g_V0[(size_t)b * HH + tid];
    __syncthreads();

    // ================= routing (R8 stream, proven) ============================
    const float cap = capacity[b];
    float rem = cap;
    int cur = 0;
    const float* xb = x + (size_t)b * NN * HH;

    for (int step = 0; step < T; step++) {
        float4 vreg = *(const float4*)(vsm + lane * 4);
        float cxc = cx[cur], cyc = cy[cur];
        float best = neg_inf();
        int bidx = 0;
        // warp w handles nodes n = w, w+8, ... ascending (first-index tiebreak)
        #pragma unroll 5
        for (int k = 0; k < 25; k++) {
            int n = wid + 8 * k;
            float4 xr = *(const float4*)(xb + (size_t)n * HH + lane * 4);
            float p = fmaf(xr.x, vreg.x, fmaf(xr.y, vreg.y,
                      fmaf(xr.z, vreg.z, xr.w * vreg.w)));
            #pragma unroll
            for (int off = 16; off > 0; off >>= 1)
                p += __shfl_xor_sync(0xffffffffu, p, off);
            float dx = cx[n] - cxc, dy = cy[n] - cyc;
            float s = p - 0.1f * sqrtf(dx * dx + dy * dy);
            if (n != 0 && (vis[n] || (dem[n] > rem))) s = neg_inf();
            if (s > best) { best = s; bidx = n; }     // strict >: lowest n kept
        }
        if (lane == 0) { red[wid] = best; redi[wid] = bidx; }
        __syncthreads();
        if (tid == 0) {
            float Bv = red[0]; int Bi = redi[0];
            #pragma unroll
            for (int w = 1; w < 8; w++) {
                float v = red[w]; int i2 = redi[w];
                if (v > Bv || (v == Bv && i2 < Bi)) { Bv = v; Bi = i2; }
            }
            nxtp[0] = Bi;
            vis[Bi] = 1;
            out[(size_t)b * T + step] = (float)Bi;
        }
        __syncthreads();
        int nxt = nxtp[0];
        rem = (nxt == 0) ? cap : (rem - dem[nxt]);
        int prev = cur;
        cur = nxt;
        // depot fixed point: identical state recurs -> remaining actions all 0
        // (row already zeroed by this CTA). Exact, not approximate.
        if (prev == 0 && nxt == 0) break;

        // ---- live path (rare): v = W^T (W x_cur + bias) ----------------------
        if (tid < 32)
            *(float4*)(xrow + tid * 4) = *(const float4*)(xb + (size_t)cur * HH + tid * 4);
        __syncthreads();
        {   // q[o] = W[o,:]·xrow + bias[o], warp-per-row
            float4 xc = *(const float4*)(xrow + lane * 4);
            #pragma unroll
            for (int r = 0; r < 16; r++) {
                int o = wid + r * 8;
                float4 w4 = *(const float4*)(W + (size_t)o * HH + lane * 4);
                float p = fmaf(w4.x, xc.x, fmaf(w4.y, xc.y,
                          fmaf(w4.z, xc.z, w4.w * xc.w)));
                #pragma unroll
                for (int off = 16; off > 0; off >>= 1)
                    p += __shfl_xor_sync(0xffffffffu, p, off);
                if (lane == 0) qsm[o] = p + bias[o];
            }
        }
        __syncthreads();
        {   // v[h] = sum_o W[o][h] q[o], coalesced columns, o halved
            int h = tid & 127, half = tid >> 7;
            float acc = 0.f;
            const float* Wp = W + (size_t)(half * 64) * HH + h;
            const float* qp = qsm + half * 64;
            #pragma unroll 8
            for (int o = 0; o < 64; o++)
                acc = fmaf(Wp[(size_t)o * HH], qp[o], acc);
            if (half == 0) vsm[h] = acc; else vpart[h] = acc;
        }
        __syncthreads();
        if (tid < HH) vsm[tid] += vpart[tid];
        __syncthreads();
    }
}

extern "C" void kernel_launch(void* const* d_in, const int* in_sizes, int n_in,
                              void* d_out, int out_size) {
    const float* x        = (const float*)d_in[0];
    const float* W        = (const float*)d_in[1];
    const float* bias     = (const float*)d_in[2];
    const float* coords   = (const float*)d_in[3];
    const float* demands  = (const float*)d_in[4];
    const float* capacity = (const float*)d_in[5];
    const int*   nsteps   = (n_in > 6) ? (const int*)d_in[6] : nullptr;
    float* out = (float*)d_out;

    k_route<<<BB, 256>>>(x, W, bias, coords, demands, capacity, nsteps, out, out_size);
}

// round 14
// speedup vs baseline: 1.5718x; 1.2942x over previous
#include <cuda_runtime.h>
#include <cstdint>
#include <math.h>

#define BB 2048
#define NN 200
#define HH 128
#define TT 180
#define NGRP 128          // producer groups, 16 batches each

__device__ float g_V0[BB * HH];   // V0[b] = W^T (W x[b,0] + bias)
__device__ int   g_flag[NGRP];    // zero-init; set stays benign across replays

__device__ __forceinline__ float neg_inf() { return __int_as_float(0xff800000); }

__global__ void __launch_bounds__(256, 6)
k_route(const float* __restrict__ x, const float* __restrict__ W,
        const float* __restrict__ bias, const float* __restrict__ coords,
        const float* __restrict__ demands, const float* __restrict__ capacity,
        const int* __restrict__ nsteps, float* __restrict__ out, int out_size) {
    __shared__ float buf[4096];                  // 16KB union
    // ---- route-phase aliases ----
    float* cx   = buf;            float* cy    = buf + 200;
    float* dem  = buf + 400;      int*   vis   = (int*)(buf + 600);
    float* vsm  = buf + 800;      float* vpart = buf + 928;
    float* qsm  = buf + 1056;     float* xrow  = buf + 1184;
    float* red  = buf + 1312;     int*   redi  = (int*)(buf + 1344);
    int*   nxtp = (int*)(buf + 1376);
    // ---- producer-phase aliases (used before route arrays are written) ----
    float* xs = buf;              // [16][128]
    float* qs = buf + 2048;       // [16][128]

    const int tid  = threadIdx.x;
    const int b    = blockIdx.x;
    const int lane = tid & 31;
    const int wid  = tid >> 5;
    const int g    = lane >> 3;      // 8-lane group 0..3
    const int j    = lane & 7;       // lane-in-group
    const int nbase = wid + 8 * g;   // 0..31
    const int T    = nsteps ? nsteps[0] : TT;

    // ================= producers: CTA g computes V0 for batches 16g..16g+15 ==
    if (b < NGRP) {
        const int gb0 = b * 16;
        for (int idx = tid; idx < 16 * 32; idx += 256) {
            int r = idx >> 5, jj = idx & 31;
            *(float4*)(xs + r * HH + jj * 4) =
                *(const float4*)(x + (size_t)(gb0 + r) * NN * HH + jj * 4);
        }
        __syncthreads();
        {   // phase 1: q[j][o] = W[o,:]·x0[j] + bias[o]
            const int o = tid & 127, jb = (tid >> 7) * 8;
            float acc[8];
            float bo = bias[o];
            #pragma unroll
            for (int jj = 0; jj < 8; jj++) acc[jj] = bo;
            for (int h = 0; h < HH; h += 4) {
                float4 w4 = *(const float4*)(W + (size_t)o * HH + h);
                #pragma unroll
                for (int jj = 0; jj < 8; jj++) {
                    float4 xv = *(const float4*)(xs + (jb + jj) * HH + h);
                    acc[jj] = fmaf(w4.x, xv.x, fmaf(w4.y, xv.y,
                              fmaf(w4.z, xv.z, fmaf(w4.w, xv.w, acc[jj]))));
                }
            }
            #pragma unroll
            for (int jj = 0; jj < 8; jj++) qs[(jb + jj) * HH + o] = acc[jj];
        }
        __syncthreads();
        {   // phase 2: V0[j][h] = sum_o W[o][h] q[j][o]
            const int h = tid & 127, jb = (tid >> 7) * 8;
            float acc[8];
            #pragma unroll
            for (int jj = 0; jj < 8; jj++) acc[jj] = 0.f;
            #pragma unroll 4
            for (int o = 0; o < HH; o++) {
                float w = W[(size_t)o * HH + h];
                #pragma unroll
                for (int jj = 0; jj < 8; jj++)
                    acc[jj] = fmaf(w, qs[(jb + jj) * HH + o], acc[jj]);
            }
            #pragma unroll
            for (int jj = 0; jj < 8; jj++)
                g_V0[(size_t)(gb0 + jb + jj) * HH + h] = acc[jj];
        }
        __threadfence();
        __syncthreads();
        if (tid == 0) atomicExch(&g_flag[b], 1);
    }

    // ================= prologue (overlaps with producers) =====================
    if (tid < T) out[(size_t)b * T + tid] = 0.0f;        // own action row
    {
        long long tail = (long long)out_size - (long long)BB * T;
        if (tail > 0) {                                   // share of log_probs tail
            int chunk = (int)((tail + BB - 1) / BB);
            long long s0 = (long long)BB * T + (long long)b * chunk;
            for (int i = tid; i < chunk; i += 256) {
                long long idx = s0 + i;
                if (idx < out_size) out[idx] = 0.0f;
            }
        }
    }
    __syncthreads();                                      // producer scratch dead
    {
        const float2* cb2 = (const float2*)(coords + (size_t)b * NN * 2);
        const float*  db  = demands + (size_t)b * NN;
        if (tid < NN) {
            float2 c2 = cb2[tid];
            cx[tid] = c2.x; cy[tid] = c2.y;
            dem[tid] = db[tid];
            vis[tid] = 0;
        }
    }
    // wait for this batch's V0 (producers are all wave-1 resident: no deadlock)
    if (tid == 0) {
        while (atomicAdd(&g_flag[b >> 4], 0) == 0) __nanosleep(64);
        __threadfence();
    }
    __syncthreads();
    if (tid < HH) vsm[tid] = g_V0[(size_t)b * HH + tid];
    __syncthreads();

    // ================= routing: grouped 8-lane stream =========================
    const float cap = capacity[b];
    float rem = cap;
    int cur = 0;
    const float* xb = x + (size_t)b * NN * HH;

    for (int step = 0; step < T; step++) {
        // lane j covers h = 32*i + 4j .. +3, i=0..3
        float4 vr0 = *(const float4*)(vsm +   0 + j * 4);
        float4 vr1 = *(const float4*)(vsm +  32 + j * 4);
        float4 vr2 = *(const float4*)(vsm +  64 + j * 4);
        float4 vr3 = *(const float4*)(vsm +  96 + j * 4);
        float cxc = cx[cur], cyc = cy[cur];

        float best = neg_inf();
        int bidx = NN;
        // group handles nodes n = nbase + 32k, ascending (strict > keeps lowest)
        #pragma unroll 7
        for (int k = 0; k < 7; k++) {
            int n = nbase + 32 * k;
            bool valid = (n < NN);
            float p = 0.f;
            if (valid) {
                const float* xr = xb + (size_t)n * HH + j * 4;
                float4 a0 = *(const float4*)(xr);
                float4 a1 = *(const float4*)(xr + 32);
                float4 a2 = *(const float4*)(xr + 64);
                float4 a3 = *(const float4*)(xr + 96);
                p = fmaf(a0.x, vr0.x, fmaf(a0.y, vr0.y, fmaf(a0.z, vr0.z, a0.w * vr0.w)));
                p = fmaf(a1.x, vr1.x, fmaf(a1.y, vr1.y, fmaf(a1.z, vr1.z, fmaf(a1.w, vr1.w, p))));
                p = fmaf(a2.x, vr2.x, fmaf(a2.y, vr2.y, fmaf(a2.z, vr2.z, fmaf(a2.w, vr2.w, p))));
                p = fmaf(a3.x, vr3.x, fmaf(a3.y, vr3.y, fmaf(a3.z, vr3.z, fmaf(a3.w, vr3.w, p))));
            }
            // 3-level butterfly within the 8-lane group (4 nodes reduced at once)
            p += __shfl_xor_sync(0xffffffffu, p, 4);
            p += __shfl_xor_sync(0xffffffffu, p, 2);
            p += __shfl_xor_sync(0xffffffffu, p, 1);
            float s = neg_inf();
            if (valid) {
                float dx = cx[n] - cxc, dy = cy[n] - cyc;
                s = p - 0.1f * sqrtf(dx * dx + dy * dy);
                if (n != 0 && (vis[n] || (dem[n] > rem))) s = neg_inf();
            }
            if (s > best) { best = s; bidx = n; }
        }
        if (j == 0) { red[wid * 4 + g] = best; redi[wid * 4 + g] = bidx; }
        __syncthreads();
        // warp 0: tie-broken argmax over 32 candidates (first-index rule)
        if (wid == 0) {
            float bv = red[lane]; int bi = redi[lane];
            #pragma unroll
            for (int off = 16; off > 0; off >>= 1) {
                float ov = __shfl_xor_sync(0xffffffffu, bv, off);
                int   oi = __shfl_xor_sync(0xffffffffu, bi, off);
                if (ov > bv || (ov == bv && oi < bi)) { bv = ov; bi = oi; }
            }
            if (lane == 0) {
                nxtp[0] = bi;
                vis[bi] = 1;
                out[(size_t)b * T + step] = (float)bi;
            }
        }
        __syncthreads();
        int nxt = nxtp[0];
        rem = (nxt == 0) ? cap : (rem - dem[nxt]);
        int prev = cur;
        cur = nxt;
        // depot fixed point: identical state recurs -> remaining actions all 0
        // (row already zeroed by this CTA). Exact, not approximate.
        if (prev == 0 && nxt == 0) break;

        // ---- live path (rare): v = W^T (W x_cur + bias) ----------------------
        if (tid < 32)
            *(float4*)(xrow + tid * 4) = *(const float4*)(xb + (size_t)cur * HH + tid * 4);
        __syncthreads();
        {   // q[o] = W[o,:]·xrow + bias[o], warp-per-row
            float4 xc = *(const float4*)(xrow + lane * 4);
            #pragma unroll
            for (int r = 0; r < 16; r++) {
                int o = wid + r * 8;
                float4 w4 = *(const float4*)(W + (size_t)o * HH + lane * 4);
                float p = fmaf(w4.x, xc.x, fmaf(w4.y, xc.y,
                          fmaf(w4.z, xc.z, w4.w * xc.w)));
                #pragma unroll
                for (int off = 16; off > 0; off >>= 1)
                    p += __shfl_xor_sync(0xffffffffu, p, off);
                if (lane == 0) qsm[o] = p + bias[o];
            }
        }
        __syncthreads();
        {   // v[h] = sum_o W[o][h] q[o], coalesced columns, o halved
            int h = tid & 127, half = tid >> 7;
            float acc = 0.f;
            const float* Wp = W + (size_t)(half * 64) * HH + h;
            const float* qp = qsm + half * 64;
            #pragma unroll 8
            for (int o = 0; o < 64; o++)
                acc = fmaf(Wp[(size_t)o * HH], qp[o], acc);
            if (half == 0) vsm[h] = acc; else vpart[h] = acc;
        }
        __syncthreads();
        if (tid < HH) vsm[tid] += vpart[tid];
        __syncthreads();
    }
}

extern "C" void kernel_launch(void* const* d_in, const int* in_sizes, int n_in,
                              void* d_out, int out_size) {
    const float* x        = (const float*)d_in[0];
    const float* W        = (const float*)d_in[1];
    const float* bias     = (const float*)d_in[2];
    const float* coords   = (const float*)d_in[3];
    const float* demands  = (const float*)d_in[4];
    const float* capacity = (const float*)d_in[5];
    const int*   nsteps   = (n_in > 6) ? (const int*)d_in[6] : nullptr;
    float* out = (float*)d_out;

    k_route<<<BB, 256>>>(x, W, bias, coords, demands, capacity, nsteps, out, out_size);
}